// round 13
// baseline (speedup 1.0000x reference)
#include <cuda_runtime.h>
#include <cuda_fp16.h>
#include <cstdint>

// ---------------------------------------------------------------------------
// MultiHeadAttention on GB300 (sm_103a) — legacy mma.sync fp16, 1-term GEMMs.
// R13: R11 dataflow (separate softmax+PV; R12 fusion was neutral) with BK=64
// K-stages (32KB/stage, 3-buffer ring, 2 stages in flight) to halve per-stage
// sync overhead, plus a no-op kernel so the profiled launch slot (#3) holds
// the QKV projection GEMM.
// ---------------------------------------------------------------------------

using f16 = __half;

static constexpr long long QKV_ELEMS = 8LL * 1024 * 2048;    // 16,777,216
static constexpr long long W_ELEMS   = 128LL * 1024 * 1024;  // 134,217,728
static constexpr long long WW_ELEMS  = 2048LL * 2048;        // 4,194,304

__device__ f16 g_xq[QKV_ELEMS], g_xk[QKV_ELEMS], g_xv[QKV_ELEMS];
__device__ f16 g_wq[WW_ELEMS], g_wk[WW_ELEMS], g_wv[WW_ELEMS], g_wo[WW_ELEMS];
__device__ f16 g_Qh[QKV_ELEMS], g_Kh[QKV_ELEMS], g_Vh[QKV_ELEMS];
__device__ f16 g_Vth[QKV_ELEMS];
__device__ f16 g_P[W_ELEMS];          // fp16 scores, then probabilities
__device__ f16 g_Ah[QKV_ELEMS];
__device__ float g_WS[W_ELEMS];       // fallback weights if d_out lacks tail

// ------------------------- asm helpers --------------------------------------

__device__ __forceinline__ uint32_t smem_u32(const void* p) {
    uint32_t a;
    asm("{ .reg .u64 t; cvta.to.shared.u64 t, %1; cvt.u32.u64 %0, t; }"
        : "=r"(a) : "l"(p));
    return a;
}

__device__ __forceinline__ void cp16(uint32_t dst, const void* src) {
    asm volatile("cp.async.cg.shared.global [%0], [%1], 16;"
                 :: "r"(dst), "l"(src));
}

__device__ __forceinline__ void ldm_x4(uint32_t* r, uint32_t addr) {
    asm volatile("ldmatrix.sync.aligned.m8n8.x4.shared.b16 {%0,%1,%2,%3}, [%4];"
                 : "=r"(r[0]), "=r"(r[1]), "=r"(r[2]), "=r"(r[3]) : "r"(addr));
}

__device__ __forceinline__ void mma16816(float* c, const uint32_t* a,
                                         uint32_t b0, uint32_t b1) {
    asm volatile(
        "mma.sync.aligned.m16n8k16.row.col.f32.f16.f16.f32 "
        "{%0,%1,%2,%3}, {%4,%5,%6,%7}, {%8,%9}, {%0,%1,%2,%3};"
        : "+f"(c[0]), "+f"(c[1]), "+f"(c[2]), "+f"(c[3])
        : "r"(a[0]), "r"(a[1]), "r"(a[2]), "r"(a[3]), "r"(b0), "r"(b1));
}

__device__ __forceinline__ uint32_t round2h(float v0, float v1) {
    return (uint32_t)__half_as_ushort(__float2half_rn(v0)) |
           ((uint32_t)__half_as_ushort(__float2half_rn(v1)) << 16);
}

// SW128 swizzle for 128-byte rows (8 chunks of 16B, XOR with row%8)
__device__ __forceinline__ uint32_t swz128(int row, int cq) {
    return (uint32_t)(row * 128 + ((cq ^ (row & 7)) << 4));
}

// ------------------------- GEMM ---------------------------------------------
// NT: C[m,n] = sum_k A[m,k] * B[n,k], K-major fp16, 1 MMA term, BK=64.
// CTA tile 128x128, 8 warps of 32x64, occupancy 2, 3-buffer ring (2 in flight).
// EPI: 0 = fused QKV (3-way select, f16+bias) | 1 = f16*scale
//      2 = f16 | 3 = f32+bias

#define T_B    16384
#define STAGE  32768
#define NBUF   3
#define SMEM_TOTAL 98304

template <int EPI>
__global__ __launch_bounds__(256, 2)
void gemm_mma(const f16* __restrict__ A0, const f16* __restrict__ A1,
              const f16* __restrict__ A2,
              const f16* __restrict__ B0, const f16* __restrict__ B1,
              const f16* __restrict__ B2,
              const float* __restrict__ bias0, const float* __restrict__ bias1,
              const float* __restrict__ bias2,
              float* __restrict__ Cf,
              f16* __restrict__ C0, f16* __restrict__ C1, f16* __restrict__ C2,
              int K, int lda, int ldb, int ldc,
              long long sA, long long sB, long long sC, float scale)
{
    extern __shared__ char smem[];
    const uint32_t sb = smem_u32(smem);
    const int tid = threadIdx.x;
    const int wid = tid >> 5;
    const int lane = tid & 31;
    const int warpM = wid >> 1;          // 0..3 (m tile 32)
    const int warpN = wid & 1;           // 0..1 (n tile 64)

    const int m0 = blockIdx.y * 128;
    const int n0g = blockIdx.x * 128;

    const f16* A;
    const f16* B;
    const float* bias;
    f16* Ch;
    int n0;
    if (EPI == 0) {
        const int sel = n0g >> 11;       // 0:Q 1:K 2:V
        n0 = n0g & 2047;
        A    = (sel == 0) ? A0 : (sel == 1) ? A1 : A2;
        B    = (sel == 0) ? B0 : (sel == 1) ? B1 : B2;
        bias = (sel == 0) ? bias0 : (sel == 1) ? bias1 : bias2;
        Ch   = (sel == 0) ? C0 : (sel == 1) ? C1 : C2;
    } else {
        const long long z = blockIdx.z;
        n0 = n0g;
        A = A0 + z * sA;
        B = B0 + z * sB;
        bias = bias0;
        Ch = (EPI == 3) ? nullptr : C0 + z * sC;
        if (EPI == 3) Cf += z * sC;
    }

    const int NS = K >> 6;               // BK = 64
    const int lrow = tid >> 1;           // 0..127
    const int lcq0 = (tid & 1) * 4;      // chunks {0..3} or {4..7}

    auto issue_stage = [&](int s, int buf) {
        const int k0 = s << 6;
        const uint32_t base = sb + buf * STAGE;
        #pragma unroll
        for (int t = 0; t < 4; t++) {
            const int cq = lcq0 + t;
            const uint32_t so = swz128(lrow, cq);
            cp16(base + so, A + (size_t)(m0 + lrow) * lda + k0 + cq * 8);
            cp16(base + T_B + so, B + (size_t)(n0 + lrow) * ldb + k0 + cq * 8);
        }
        asm volatile("cp.async.commit_group;");
    };

    float acc[2][8][4];
    #pragma unroll
    for (int mt = 0; mt < 2; mt++)
        #pragma unroll
        for (int nt = 0; nt < 8; nt++)
            #pragma unroll
            for (int j = 0; j < 4; j++)
                acc[mt][nt][j] = 0.f;

    const int frow = lane & 15;
    const int fhi  = lane >> 4;

    issue_stage(0, 0);
    if (NS > 1) issue_stage(1, 1);
    else asm volatile("cp.async.commit_group;");

    int buf = 0;
    for (int s = 0; s < NS; s++) {
        asm volatile("cp.async.wait_group 1;");
        __syncthreads();
        {
            int nb = buf + 2; if (nb >= NBUF) nb -= NBUF;
            if (s + 2 < NS) issue_stage(s + 2, nb);
            else asm volatile("cp.async.commit_group;");
        }

        const uint32_t stb = sb + buf * STAGE;
        #pragma unroll
        for (int kq = 0; kq < 4; kq++) {
            uint32_t aH[2][4];
            #pragma unroll
            for (int mt = 0; mt < 2; mt++) {
                const int row = warpM * 32 + mt * 16 + frow;
                ldm_x4(aH[mt], stb + swz128(row, kq * 2 + fhi));
            }
            #pragma unroll
            for (int half = 0; half < 2; half++) {
                uint32_t bH[2][4];
                #pragma unroll
                for (int g = 0; g < 2; g++) {
                    const int row = warpN * 64 + (half * 2 + g) * 16 + frow;
                    ldm_x4(bH[g], stb + T_B + swz128(row, kq * 2 + fhi));
                }
                #pragma unroll
                for (int mt = 0; mt < 2; mt++)
                    #pragma unroll
                    for (int t4 = 0; t4 < 4; t4++) {
                        const int g = t4 >> 1, rs = t4 & 1;
                        mma16816(acc[mt][half * 4 + t4], aH[mt],
                                 bH[g][rs], bH[g][rs + 2]);
                    }
            }
        }
        if (++buf == NBUF) buf = 0;
    }
    asm volatile("cp.async.wait_group 0;");
    __syncthreads();

    // ---- epilogue: stage fp32 tile in SMEM, then coalesced global writes ----
    {
        const int PITCH = 132;
        float* st = (float*)smem;
        const int tr = lane >> 2;
        const int tc = (lane & 3) * 2;
        #pragma unroll
        for (int mt = 0; mt < 2; mt++)
            #pragma unroll
            for (int nt = 0; nt < 8; nt++) {
                const int r0 = warpM * 32 + mt * 16 + tr;
                const int c0 = warpN * 64 + nt * 8 + tc;
                st[r0 * PITCH + c0]           = acc[mt][nt][0];
                st[r0 * PITCH + c0 + 1]       = acc[mt][nt][1];
                st[(r0 + 8) * PITCH + c0]     = acc[mt][nt][2];
                st[(r0 + 8) * PITCH + c0 + 1] = acc[mt][nt][3];
            }
        __syncthreads();

        const int orow = tid >> 1;
        const int ocb  = (tid & 1) * 64;
        const float* src = st + orow * PITCH + ocb;
        const size_t cbase = (size_t)(m0 + orow) * ldc + n0 + ocb;

        if (EPI == 3) {
            #pragma unroll
            for (int j = 0; j < 64; j += 4) {
                float4 v = *(const float4*)(src + j);
                const float4 b = *(const float4*)(bias + n0 + ocb + j);
                v.x += b.x; v.y += b.y; v.z += b.z; v.w += b.w;
                *(float4*)(Cf + cbase + j) = v;
            }
        } else if (EPI == 0) {
            #pragma unroll
            for (int j = 0; j < 64; j += 2) {
                const float v0 = src[j] + bias[n0 + ocb + j];
                const float v1 = src[j + 1] + bias[n0 + ocb + j + 1];
                *(uint32_t*)(Ch + cbase + j) = round2h(v0, v1);
            }
        } else if (EPI == 1) {
            #pragma unroll
            for (int j = 0; j < 64; j += 2)
                *(uint32_t*)(Ch + cbase + j) =
                    round2h(src[j] * scale, src[j + 1] * scale);
        } else {  // EPI == 2
            #pragma unroll
            for (int j = 0; j < 64; j += 2)
                *(uint32_t*)(Ch + cbase + j) = round2h(src[j], src[j + 1]);
        }
    }
}

// ------------------------- aux kernels --------------------------------------

__global__ void dummy_k() {}   // occupies a launch slot so ncu profiles the GEMM

__global__ __launch_bounds__(256)
void round3_kernel(const float* __restrict__ x0, f16* __restrict__ h0,
                   const float* __restrict__ x1, f16* __restrict__ h1,
                   const float* __restrict__ x2, f16* __restrict__ h2)
{
    const float* x; f16* h;
    if (blockIdx.z == 0)      { x = x0; h = h0; }
    else if (blockIdx.z == 1) { x = x1; h = h1; }
    else                      { x = x2; h = h2; }
    const long long i = (long long)blockIdx.x * 256 + threadIdx.x;
    const float4 v = ((const float4*)x)[i];
    uint2 hu;
    hu.x = round2h(v.x, v.y);
    hu.y = round2h(v.z, v.w);
    ((uint2*)h)[i] = hu;
}

__global__ __launch_bounds__(256)
void round4_kernel(const float* __restrict__ x0, f16* __restrict__ h0,
                   const float* __restrict__ x1, f16* __restrict__ h1,
                   const float* __restrict__ x2, f16* __restrict__ h2,
                   const float* __restrict__ x3, f16* __restrict__ h3)
{
    const float* x; f16* h;
    if (blockIdx.z == 0)      { x = x0; h = h0; }
    else if (blockIdx.z == 1) { x = x1; h = h1; }
    else if (blockIdx.z == 2) { x = x2; h = h2; }
    else                      { x = x3; h = h3; }
    const long long i = (long long)blockIdx.x * 256 + threadIdx.x;
    const float4 v = ((const float4*)x)[i];
    uint2 hu;
    hu.x = round2h(v.x, v.y);
    hu.y = round2h(v.z, v.w);
    ((uint2*)h)[i] = hu;
}

// per-slab [1024,128] -> [128,1024] transpose of fp16 V
__global__ __launch_bounds__(256)
void transpose_v(const f16* __restrict__ vh, f16* __restrict__ vth)
{
    __shared__ f16 th[32][33];
    const int g = blockIdx.z;
    const int d0 = blockIdx.x * 32;
    const int k0 = blockIdx.y * 32;
    const size_t ib = (size_t)g * 131072;
    const int tx = threadIdx.x & 31;
    const int ty = threadIdx.x >> 5;
    #pragma unroll
    for (int i = 0; i < 4; i++) {
        const int k = k0 + ty + i * 8;
        th[ty + i * 8][tx] = vh[ib + (size_t)k * 128 + d0 + tx];
    }
    __syncthreads();
    #pragma unroll
    for (int i = 0; i < 4; i++) {
        const int d = d0 + ty + i * 8;
        vth[ib + (size_t)d * 1024 + k0 + tx] = th[tx][ty + i * 8];
    }
}

// row softmax: 2 rows per 256-thread block, 8 halves per thread (uint4).
__global__ __launch_bounds__(256)
void softmax1024(f16* __restrict__ p, float* __restrict__ wf)
{
    __shared__ float smax[8];
    __shared__ float ssum[8];
    const int tid = threadIdx.x;
    const int wid = tid >> 5;
    const int rsel = tid >> 7;
    const int t = tid & 127;
    const size_t rb = ((size_t)blockIdx.x * 2 + rsel) * 1024;

    const uint4 raw = ((const uint4*)(p + rb))[t];
    float v[8];
    {
        const __half2 h0 = *(const __half2*)&raw.x;
        const __half2 h1 = *(const __half2*)&raw.y;
        const __half2 h2 = *(const __half2*)&raw.z;
        const __half2 h3 = *(const __half2*)&raw.w;
        v[0] = __low2float(h0); v[1] = __high2float(h0);
        v[2] = __low2float(h1); v[3] = __high2float(h1);
        v[4] = __low2float(h2); v[5] = __high2float(h2);
        v[6] = __low2float(h3); v[7] = __high2float(h3);
    }

    float m = v[0];
    #pragma unroll
    for (int j = 1; j < 8; j++) m = fmaxf(m, v[j]);
    #pragma unroll
    for (int o = 16; o > 0; o >>= 1)
        m = fmaxf(m, __shfl_xor_sync(0xffffffffu, m, o));
    if ((tid & 31) == 0) smax[wid] = m;
    __syncthreads();
    const int wb = rsel * 4;
    const float bm = fmaxf(fmaxf(smax[wb], smax[wb + 1]),
                           fmaxf(smax[wb + 2], smax[wb + 3]));

    float s = 0.f;
    #pragma unroll
    for (int j = 0; j < 8; j++) { v[j] = __expf(v[j] - bm); s += v[j]; }
    #pragma unroll
    for (int o = 16; o > 0; o >>= 1)
        s += __shfl_xor_sync(0xffffffffu, s, o);
    if ((tid & 31) == 0) ssum[wid] = s;
    __syncthreads();
    const float inv = 1.0f / (ssum[wb] + ssum[wb + 1] +
                              ssum[wb + 2] + ssum[wb + 3]);
    #pragma unroll
    for (int j = 0; j < 8; j++) v[j] *= inv;

    ((float4*)(wf + rb))[t * 2]     = make_float4(v[0], v[1], v[2], v[3]);
    ((float4*)(wf + rb))[t * 2 + 1] = make_float4(v[4], v[5], v[6], v[7]);
    uint4 o4;
    o4.x = round2h(v[0], v[1]);
    o4.y = round2h(v[2], v[3]);
    o4.z = round2h(v[4], v[5]);
    o4.w = round2h(v[6], v[7]);
    ((uint4*)(p + rb))[t] = o4;
}

// ------------------------- launcher -----------------------------------------

extern "C" void kernel_launch(void* const* d_in, const int* in_sizes, int n_in,
                              void* d_out, int out_size)
{
    (void)in_sizes; (void)n_in;
    const float* query = (const float*)d_in[0];
    const float* key   = (const float*)d_in[1];
    const float* value = (const float*)d_in[2];
    const float* Wq_w  = (const float*)d_in[3];
    const float* Wq_b  = (const float*)d_in[4];
    const float* Wk_w  = (const float*)d_in[5];
    const float* Wk_b  = (const float*)d_in[6];
    const float* Wv_w  = (const float*)d_in[7];
    const float* Wv_b  = (const float*)d_in[8];
    const float* Wo_w  = (const float*)d_in[9];
    const float* Wo_b  = (const float*)d_in[10];

    f16 *xq, *xk, *xv, *wq, *wk, *wv, *wo;
    f16 *Qh, *Kh, *Vh, *Vth, *P, *Ahb;
    float* WS;
    cudaGetSymbolAddress((void**)&xq, g_xq);   cudaGetSymbolAddress((void**)&xk, g_xk);
    cudaGetSymbolAddress((void**)&xv, g_xv);
    cudaGetSymbolAddress((void**)&wq, g_wq);   cudaGetSymbolAddress((void**)&wk, g_wk);
    cudaGetSymbolAddress((void**)&wv, g_wv);   cudaGetSymbolAddress((void**)&wo, g_wo);
    cudaGetSymbolAddress((void**)&Qh, g_Qh);   cudaGetSymbolAddress((void**)&Kh, g_Kh);
    cudaGetSymbolAddress((void**)&Vh, g_Vh);   cudaGetSymbolAddress((void**)&Vth, g_Vth);
    cudaGetSymbolAddress((void**)&P, g_P);     cudaGetSymbolAddress((void**)&Ahb, g_Ah);
    cudaGetSymbolAddress((void**)&WS, g_WS);

    float* out = (float*)d_out;
    float* weights = ((long long)out_size >= QKV_ELEMS + W_ELEMS)
                         ? out + QKV_ELEMS : WS;

    cudaFuncSetAttribute(gemm_mma<0>, cudaFuncAttributeMaxDynamicSharedMemorySize, SMEM_TOTAL);
    cudaFuncSetAttribute(gemm_mma<1>, cudaFuncAttributeMaxDynamicSharedMemorySize, SMEM_TOTAL);
    cudaFuncSetAttribute(gemm_mma<2>, cudaFuncAttributeMaxDynamicSharedMemorySize, SMEM_TOTAL);
    cudaFuncSetAttribute(gemm_mma<3>, cudaFuncAttributeMaxDynamicSharedMemorySize, SMEM_TOTAL);

    const float inv_sqrt_d = 0.022097086912079608f;  // 1/sqrt(2048)
    dim3 blk(256);

    // #0, #1: preprocessing; #2: dummy (slot filler); #3: QKV GEMM (profiled)
    round3_kernel<<<dim3(16384, 1, 3), blk>>>(query, xq, key, xk, value, xv);
    round4_kernel<<<dim3(4096, 1, 4), blk>>>(Wq_w, wq, Wk_w, wk, Wv_w, wv, Wo_w, wo);
    dummy_k<<<1, 32>>>();

    gemm_mma<0><<<dim3(48, 64, 1), blk, SMEM_TOTAL>>>(
        xq, xk, xv, wq, wk, wv, Wq_b, Wk_b, Wv_b,
        nullptr, Qh, Kh, Vh,
        2048, 2048, 2048, 2048, 0, 0, 0, 1.f);

    transpose_v<<<dim3(4, 32, 128), blk>>>(Vh, Vth);

    // scores = Q K^T * scale per contiguous slab -> fp16 P buffer
    gemm_mma<1><<<dim3(8, 8, 128), blk, SMEM_TOTAL>>>(
        Qh, nullptr, nullptr, Kh, nullptr, nullptr, nullptr, nullptr, nullptr,
        nullptr, P, nullptr, nullptr,
        128, 128, 128, 1024,
        131072LL, 131072LL, 1048576LL, inv_sqrt_d);

    // softmax: fp16 in-place + fp32 weights out (2 rows per block)
    softmax1024<<<65536, blk>>>(P, weights);

    // attn = P Vt^T -> fp16
    gemm_mma<2><<<dim3(1, 8, 128), blk, SMEM_TOTAL>>>(
        P, nullptr, nullptr, Vth, nullptr, nullptr, nullptr, nullptr, nullptr,
        nullptr, Ahb, nullptr, nullptr,
        1024, 1024, 1024, 128,
        1048576LL, 131072LL, 131072LL, 1.f);

    // out = attn Wo^T + b -> fp32
    gemm_mma<3><<<dim3(16, 64, 1), blk, SMEM_TOTAL>>>(
        Ahb, nullptr, nullptr, wo, nullptr, nullptr, Wo_b, nullptr, nullptr,
        out, nullptr, nullptr, nullptr,
        2048, 2048, 2048, 2048, 0, 0, 0, 1.f);
}

// round 14
// speedup vs baseline: 1.0284x; 1.0284x over previous
#include <cuda_runtime.h>
#include <cuda_fp16.h>
#include <cstdint>

// ---------------------------------------------------------------------------
// MultiHeadAttention on GB300 (sm_103a) — legacy mma.sync fp16, 1-term GEMMs.
// R14: R11 base (BK=32, 5-buffer cp.async ring, occ 2) + register-level
// double-buffering of ldmatrix fragments: step s+1's LDSM issues before step
// s's MMAs, breaking the LDSM->MMA short-scoreboard chain (R13 ncu showed
// tensor pipe at only 40.5%, issue 22% on the projection GEMM).
// ---------------------------------------------------------------------------

using f16 = __half;

static constexpr long long QKV_ELEMS = 8LL * 1024 * 2048;    // 16,777,216
static constexpr long long W_ELEMS   = 128LL * 1024 * 1024;  // 134,217,728
static constexpr long long WW_ELEMS  = 2048LL * 2048;        // 4,194,304

__device__ f16 g_xq[QKV_ELEMS], g_xk[QKV_ELEMS], g_xv[QKV_ELEMS];
__device__ f16 g_wq[WW_ELEMS], g_wk[WW_ELEMS], g_wv[WW_ELEMS], g_wo[WW_ELEMS];
__device__ f16 g_Qh[QKV_ELEMS], g_Kh[QKV_ELEMS], g_Vh[QKV_ELEMS];
__device__ f16 g_Vth[QKV_ELEMS];
__device__ f16 g_P[W_ELEMS];          // fp16 scores, then probabilities
__device__ f16 g_Ah[QKV_ELEMS];
__device__ float g_WS[W_ELEMS];       // fallback weights if d_out lacks tail

// ------------------------- asm helpers --------------------------------------

__device__ __forceinline__ uint32_t smem_u32(const void* p) {
    uint32_t a;
    asm("{ .reg .u64 t; cvta.to.shared.u64 t, %1; cvt.u32.u64 %0, t; }"
        : "=r"(a) : "l"(p));
    return a;
}

__device__ __forceinline__ void cp16(uint32_t dst, const void* src) {
    asm volatile("cp.async.cg.shared.global [%0], [%1], 16;"
                 :: "r"(dst), "l"(src));
}

__device__ __forceinline__ void ldm_x4(uint32_t* r, uint32_t addr) {
    asm volatile("ldmatrix.sync.aligned.m8n8.x4.shared.b16 {%0,%1,%2,%3}, [%4];"
                 : "=r"(r[0]), "=r"(r[1]), "=r"(r[2]), "=r"(r[3]) : "r"(addr));
}

__device__ __forceinline__ void mma16816(float* c, const uint32_t* a,
                                         uint32_t b0, uint32_t b1) {
    asm volatile(
        "mma.sync.aligned.m16n8k16.row.col.f32.f16.f16.f32 "
        "{%0,%1,%2,%3}, {%4,%5,%6,%7}, {%8,%9}, {%0,%1,%2,%3};"
        : "+f"(c[0]), "+f"(c[1]), "+f"(c[2]), "+f"(c[3])
        : "r"(a[0]), "r"(a[1]), "r"(a[2]), "r"(a[3]), "r"(b0), "r"(b1));
}

__device__ __forceinline__ uint32_t round2h(float v0, float v1) {
    return (uint32_t)__half_as_ushort(__float2half_rn(v0)) |
           ((uint32_t)__half_as_ushort(__float2half_rn(v1)) << 16);
}

// ------------------------- GEMM ---------------------------------------------
// NT: C[m,n] = sum_k A[m,k] * B[n,k], K-major fp16, 1 MMA term.
// CTA tile 128x128, 8 warps of 32x64, occupancy 2, 5-buffer cp.async ring,
// register double-buffered ldmatrix fragments.
// EPI: 0 = fused QKV (3-way select, f16+bias) | 1 = f16*scale
//      2 = f16 | 3 = f32+bias

#define TILE8K 8192
#define STAGE  16384
#define NBUF   5
#define SMEM_TOTAL 81920   // 5 stages x 16KB; epilogue (67.6KB) reuses it

__device__ __forceinline__ uint32_t swz(int row, int cq) {
    return (uint32_t)(row * 64 + ((cq ^ ((row >> 1) & 3)) << 4));
}

template <int EPI>
__global__ __launch_bounds__(256, 2)
void gemm_mma(const f16* __restrict__ A0, const f16* __restrict__ A1,
              const f16* __restrict__ A2,
              const f16* __restrict__ B0, const f16* __restrict__ B1,
              const f16* __restrict__ B2,
              const float* __restrict__ bias0, const float* __restrict__ bias1,
              const float* __restrict__ bias2,
              float* __restrict__ Cf,
              f16* __restrict__ C0, f16* __restrict__ C1, f16* __restrict__ C2,
              int K, int lda, int ldb, int ldc,
              long long sA, long long sB, long long sC, float scale)
{
    extern __shared__ char smem[];
    const uint32_t sb = smem_u32(smem);
    const int tid = threadIdx.x;
    const int wid = tid >> 5;
    const int lane = tid & 31;
    const int warpM = wid >> 1;          // 0..3 (m tile 32)
    const int warpN = wid & 1;           // 0..1 (n tile 64)

    const int m0 = blockIdx.y * 128;
    const int n0g = blockIdx.x * 128;

    const f16* A;
    const f16* B;
    const float* bias;
    f16* Ch;
    int n0;
    if (EPI == 0) {
        const int sel = n0g >> 11;       // 0:Q 1:K 2:V
        n0 = n0g & 2047;
        A    = (sel == 0) ? A0 : (sel == 1) ? A1 : A2;
        B    = (sel == 0) ? B0 : (sel == 1) ? B1 : B2;
        bias = (sel == 0) ? bias0 : (sel == 1) ? bias1 : bias2;
        Ch   = (sel == 0) ? C0 : (sel == 1) ? C1 : C2;
    } else {
        const long long z = blockIdx.z;
        n0 = n0g;
        A = A0 + z * sA;
        B = B0 + z * sB;
        bias = bias0;
        Ch = (EPI == 3) ? nullptr : C0 + z * sC;
        if (EPI == 3) Cf += z * sC;
    }

    const int NS = K >> 5;
    const int lrow = tid >> 1;
    const int lcq0 = (tid & 1) * 2;

    auto issue_stage = [&](int s, int buf) {
        const int k0 = s << 5;
        const uint32_t base = sb + buf * STAGE;
        #pragma unroll
        for (int t = 0; t < 2; t++) {
            const int cq = lcq0 + t;
            const uint32_t so = swz(lrow, cq);
            cp16(base + so, A + (size_t)(m0 + lrow) * lda + k0 + cq * 8);
            cp16(base + TILE8K + so, B + (size_t)(n0 + lrow) * ldb + k0 + cq * 8);
        }
        asm volatile("cp.async.commit_group;");
    };

    float acc[2][8][4];
    #pragma unroll
    for (int mt = 0; mt < 2; mt++)
        #pragma unroll
        for (int nt = 0; nt < 8; nt++)
            #pragma unroll
            for (int j = 0; j < 4; j++)
                acc[mt][nt][j] = 0.f;

    const int frow = lane & 15;
    const int fhi  = lane >> 4;
    const int arow0 = warpM * 32 + frow;      // + mt*16
    const int brow0 = warpN * 64 + frow;      // + (half*2+g)*16

    #pragma unroll
    for (int i = 0; i < 4; i++) {
        if (i < NS) issue_stage(i, i);
        else asm volatile("cp.async.commit_group;");
    }

    int buf = 0;
    for (int s = 0; s < NS; s++) {
        asm volatile("cp.async.wait_group 3;");
        __syncthreads();
        {
            const int nb = (buf + 4 >= NBUF) ? buf - 1 : buf + 4;
            if (s + 4 < NS) issue_stage(s + 4, nb);
            else asm volatile("cp.async.commit_group;");
        }

        const uint32_t stb = sb + buf * STAGE;

        // register double-buffered fragments:
        // step = kq*2 + half; a parity = kq&1, b parity = step&1
        uint32_t aF[2][2][4];
        uint32_t bF[2][2][4];
        #pragma unroll
        for (int mt = 0; mt < 2; mt++)
            ldm_x4(aF[0][mt], stb + swz(arow0 + mt * 16, fhi));
        #pragma unroll
        for (int g = 0; g < 2; g++)
            ldm_x4(bF[0][g], stb + TILE8K + swz(brow0 + g * 16, fhi));

        #pragma unroll
        for (int step = 0; step < 4; step++) {
            const int kq = step >> 1, half = step & 1;
            const int ap = kq & 1, bp = step & 1;
            if (step < 3) {
                const int ns = step + 1;
                const int nkq = ns >> 1, nhalf = ns & 1;
                const int nbp = ns & 1;
                #pragma unroll
                for (int g = 0; g < 2; g++)
                    ldm_x4(bF[nbp][g],
                           stb + TILE8K +
                           swz(brow0 + (nhalf * 2 + g) * 16, nkq * 2 + fhi));
                if (nhalf == 0) {
                    #pragma unroll
                    for (int mt = 0; mt < 2; mt++)
                        ldm_x4(aF[nkq & 1][mt],
                               stb + swz(arow0 + mt * 16, nkq * 2 + fhi));
                }
            }
            #pragma unroll
            for (int mt = 0; mt < 2; mt++)
                #pragma unroll
                for (int t4 = 0; t4 < 4; t4++) {
                    const int g = t4 >> 1, rs = t4 & 1;
                    mma16816(acc[mt][half * 4 + t4], aF[ap][mt],
                             bF[bp][g][rs], bF[bp][g][rs + 2]);
                }
        }
        if (++buf == NBUF) buf = 0;
    }
    __syncthreads();

    // ---- epilogue: stage fp32 tile in SMEM, then coalesced global writes ----
    {
        const int PITCH = 132;
        float* st = (float*)smem;
        const int tr = lane >> 2;
        const int tc = (lane & 3) * 2;
        #pragma unroll
        for (int mt = 0; mt < 2; mt++)
            #pragma unroll
            for (int nt = 0; nt < 8; nt++) {
                const int r0 = warpM * 32 + mt * 16 + tr;
                const int c0 = warpN * 64 + nt * 8 + tc;
                st[r0 * PITCH + c0]           = acc[mt][nt][0];
                st[r0 * PITCH + c0 + 1]       = acc[mt][nt][1];
                st[(r0 + 8) * PITCH + c0]     = acc[mt][nt][2];
                st[(r0 + 8) * PITCH + c0 + 1] = acc[mt][nt][3];
            }
        __syncthreads();

        const int orow = tid >> 1;
        const int ocb  = (tid & 1) * 64;
        const float* src = st + orow * PITCH + ocb;
        const size_t cbase = (size_t)(m0 + orow) * ldc + n0 + ocb;

        if (EPI == 3) {
            #pragma unroll
            for (int j = 0; j < 64; j += 4) {
                float4 v = *(const float4*)(src + j);
                const float4 b = *(const float4*)(bias + n0 + ocb + j);
                v.x += b.x; v.y += b.y; v.z += b.z; v.w += b.w;
                *(float4*)(Cf + cbase + j) = v;
            }
        } else if (EPI == 0) {
            #pragma unroll
            for (int j = 0; j < 64; j += 2) {
                const float v0 = src[j] + bias[n0 + ocb + j];
                const float v1 = src[j + 1] + bias[n0 + ocb + j + 1];
                *(uint32_t*)(Ch + cbase + j) = round2h(v0, v1);
            }
        } else if (EPI == 1) {
            #pragma unroll
            for (int j = 0; j < 64; j += 2)
                *(uint32_t*)(Ch + cbase + j) =
                    round2h(src[j] * scale, src[j + 1] * scale);
        } else {  // EPI == 2
            #pragma unroll
            for (int j = 0; j < 64; j += 2)
                *(uint32_t*)(Ch + cbase + j) = round2h(src[j], src[j + 1]);
        }
    }
}

// ------------------------- aux kernels --------------------------------------

__global__ void dummy_k() {}   // slot filler so ncu profiles the QKV GEMM

__global__ __launch_bounds__(256)
void round3_kernel(const float* __restrict__ x0, f16* __restrict__ h0,
                   const float* __restrict__ x1, f16* __restrict__ h1,
                   const float* __restrict__ x2, f16* __restrict__ h2)
{
    const float* x; f16* h;
    if (blockIdx.z == 0)      { x = x0; h = h0; }
    else if (blockIdx.z == 1) { x = x1; h = h1; }
    else                      { x = x2; h = h2; }
    const long long i = (long long)blockIdx.x * 256 + threadIdx.x;
    const float4 v = ((const float4*)x)[i];
    uint2 hu;
    hu.x = round2h(v.x, v.y);
    hu.y = round2h(v.z, v.w);
    ((uint2*)h)[i] = hu;
}

__global__ __launch_bounds__(256)
void round4_kernel(const float* __restrict__ x0, f16* __restrict__ h0,
                   const float* __restrict__ x1, f16* __restrict__ h1,
                   const float* __restrict__ x2, f16* __restrict__ h2,
                   const float* __restrict__ x3, f16* __restrict__ h3)
{
    const float* x; f16* h;
    if (blockIdx.z == 0)      { x = x0; h = h0; }
    else if (blockIdx.z == 1) { x = x1; h = h1; }
    else if (blockIdx.z == 2) { x = x2; h = h2; }
    else                      { x = x3; h = h3; }
    const long long i = (long long)blockIdx.x * 256 + threadIdx.x;
    const float4 v = ((const float4*)x)[i];
    uint2 hu;
    hu.x = round2h(v.x, v.y);
    hu.y = round2h(v.z, v.w);
    ((uint2*)h)[i] = hu;
}

// per-slab [1024,128] -> [128,1024] transpose of fp16 V
__global__ __launch_bounds__(256)
void transpose_v(const f16* __restrict__ vh, f16* __restrict__ vth)
{
    __shared__ f16 th[32][33];
    const int g = blockIdx.z;
    const int d0 = blockIdx.x * 32;
    const int k0 = blockIdx.y * 32;
    const size_t ib = (size_t)g * 131072;
    const int tx = threadIdx.x & 31;
    const int ty = threadIdx.x >> 5;
    #pragma unroll
    for (int i = 0; i < 4; i++) {
        const int k = k0 + ty + i * 8;
        th[ty + i * 8][tx] = vh[ib + (size_t)k * 128 + d0 + tx];
    }
    __syncthreads();
    #pragma unroll
    for (int i = 0; i < 4; i++) {
        const int d = d0 + ty + i * 8;
        vth[ib + (size_t)d * 1024 + k0 + tx] = th[tx][ty + i * 8];
    }
}

// row softmax: 2 rows per 256-thread block, 8 halves per thread (uint4).
__global__ __launch_bounds__(256)
void softmax1024(f16* __restrict__ p, float* __restrict__ wf)
{
    __shared__ float smax[8];
    __shared__ float ssum[8];
    const int tid = threadIdx.x;
    const int wid = tid >> 5;
    const int rsel = tid >> 7;
    const int t = tid & 127;
    const size_t rb = ((size_t)blockIdx.x * 2 + rsel) * 1024;

    const uint4 raw = ((const uint4*)(p + rb))[t];
    float v[8];
    {
        const __half2 h0 = *(const __half2*)&raw.x;
        const __half2 h1 = *(const __half2*)&raw.y;
        const __half2 h2 = *(const __half2*)&raw.z;
        const __half2 h3 = *(const __half2*)&raw.w;
        v[0] = __low2float(h0); v[1] = __high2float(h0);
        v[2] = __low2float(h1); v[3] = __high2float(h1);
        v[4] = __low2float(h2); v[5] = __high2float(h2);
        v[6] = __low2float(h3); v[7] = __high2float(h3);
    }

    float m = v[0];
    #pragma unroll
    for (int j = 1; j < 8; j++) m = fmaxf(m, v[j]);
    #pragma unroll
    for (int o = 16; o > 0; o >>= 1)
        m = fmaxf(m, __shfl_xor_sync(0xffffffffu, m, o));
    if ((tid & 31) == 0) smax[wid] = m;
    __syncthreads();
    const int wb = rsel * 4;
    const float bm = fmaxf(fmaxf(smax[wb], smax[wb + 1]),
                           fmaxf(smax[wb + 2], smax[wb + 3]));

    float s = 0.f;
    #pragma unroll
    for (int j = 0; j < 8; j++) { v[j] = __expf(v[j] - bm); s += v[j]; }
    #pragma unroll
    for (int o = 16; o > 0; o >>= 1)
        s += __shfl_xor_sync(0xffffffffu, s, o);
    if ((tid & 31) == 0) ssum[wid] = s;
    __syncthreads();
    const float inv = 1.0f / (ssum[wb] + ssum[wb + 1] +
                              ssum[wb + 2] + ssum[wb + 3]);
    #pragma unroll
    for (int j = 0; j < 8; j++) v[j] *= inv;

    ((float4*)(wf + rb))[t * 2]     = make_float4(v[0], v[1], v[2], v[3]);
    ((float4*)(wf + rb))[t * 2 + 1] = make_float4(v[4], v[5], v[6], v[7]);
    uint4 o4;
    o4.x = round2h(v[0], v[1]);
    o4.y = round2h(v[2], v[3]);
    o4.z = round2h(v[4], v[5]);
    o4.w = round2h(v[6], v[7]);
    ((uint4*)(p + rb))[t] = o4;
}

// ------------------------- launcher -----------------------------------------

extern "C" void kernel_launch(void* const* d_in, const int* in_sizes, int n_in,
                              void* d_out, int out_size)
{
    (void)in_sizes; (void)n_in;
    const float* query = (const float*)d_in[0];
    const float* key   = (const float*)d_in[1];
    const float* value = (const float*)d_in[2];
    const float* Wq_w  = (const float*)d_in[3];
    const float* Wq_b  = (const float*)d_in[4];
    const float* Wk_w  = (const float*)d_in[5];
    const float* Wk_b  = (const float*)d_in[6];
    const float* Wv_w  = (const float*)d_in[7];
    const float* Wv_b  = (const float*)d_in[8];
    const float* Wo_w  = (const float*)d_in[9];
    const float* Wo_b  = (const float*)d_in[10];

    f16 *xq, *xk, *xv, *wq, *wk, *wv, *wo;
    f16 *Qh, *Kh, *Vh, *Vth, *P, *Ahb;
    float* WS;
    cudaGetSymbolAddress((void**)&xq, g_xq);   cudaGetSymbolAddress((void**)&xk, g_xk);
    cudaGetSymbolAddress((void**)&xv, g_xv);
    cudaGetSymbolAddress((void**)&wq, g_wq);   cudaGetSymbolAddress((void**)&wk, g_wk);
    cudaGetSymbolAddress((void**)&wv, g_wv);   cudaGetSymbolAddress((void**)&wo, g_wo);
    cudaGetSymbolAddress((void**)&Qh, g_Qh);   cudaGetSymbolAddress((void**)&Kh, g_Kh);
    cudaGetSymbolAddress((void**)&Vh, g_Vh);   cudaGetSymbolAddress((void**)&Vth, g_Vth);
    cudaGetSymbolAddress((void**)&P, g_P);     cudaGetSymbolAddress((void**)&Ahb, g_Ah);
    cudaGetSymbolAddress((void**)&WS, g_WS);

    float* out = (float*)d_out;
    float* weights = ((long long)out_size >= QKV_ELEMS + W_ELEMS)
                         ? out + QKV_ELEMS : WS;

    cudaFuncSetAttribute(gemm_mma<0>, cudaFuncAttributeMaxDynamicSharedMemorySize, SMEM_TOTAL);
    cudaFuncSetAttribute(gemm_mma<1>, cudaFuncAttributeMaxDynamicSharedMemorySize, SMEM_TOTAL);
    cudaFuncSetAttribute(gemm_mma<2>, cudaFuncAttributeMaxDynamicSharedMemorySize, SMEM_TOTAL);
    cudaFuncSetAttribute(gemm_mma<3>, cudaFuncAttributeMaxDynamicSharedMemorySize, SMEM_TOTAL);

    const float inv_sqrt_d = 0.022097086912079608f;  // 1/sqrt(2048)
    dim3 blk(256);

    // #0, #1: preprocessing; #2: dummy; #3: QKV GEMM (profiled slot)
    round3_kernel<<<dim3(16384, 1, 3), blk>>>(query, xq, key, xk, value, xv);
    round4_kernel<<<dim3(4096, 1, 4), blk>>>(Wq_w, wq, Wk_w, wk, Wv_w, wv, Wo_w, wo);
    dummy_k<<<1, 32>>>();

    gemm_mma<0><<<dim3(48, 64, 1), blk, SMEM_TOTAL>>>(
        xq, xk, xv, wq, wk, wv, Wq_b, Wk_b, Wv_b,
        nullptr, Qh, Kh, Vh,
        2048, 2048, 2048, 2048, 0, 0, 0, 1.f);

    transpose_v<<<dim3(4, 32, 128), blk>>>(Vh, Vth);

    // scores = Q K^T * scale per contiguous slab -> fp16 P buffer
    gemm_mma<1><<<dim3(8, 8, 128), blk, SMEM_TOTAL>>>(
        Qh, nullptr, nullptr, Kh, nullptr, nullptr, nullptr, nullptr, nullptr,
        nullptr, P, nullptr, nullptr,
        128, 128, 128, 1024,
        131072LL, 131072LL, 1048576LL, inv_sqrt_d);

    // softmax: fp16 in-place + fp32 weights out (2 rows per block)
    softmax1024<<<65536, blk>>>(P, weights);

    // attn = P Vt^T -> fp16
    gemm_mma<2><<<dim3(1, 8, 128), blk, SMEM_TOTAL>>>(
        P, nullptr, nullptr, Vth, nullptr, nullptr, nullptr, nullptr, nullptr,
        nullptr, Ahb, nullptr, nullptr,
        1024, 1024, 1024, 128,
        1048576LL, 131072LL, 131072LL, 1.f);

    // out = attn Wo^T + b -> fp32
    gemm_mma<3><<<dim3(16, 64, 1), blk, SMEM_TOTAL>>>(
        Ahb, nullptr, nullptr, wo, nullptr, nullptr, Wo_b, nullptr, nullptr,
        out, nullptr, nullptr, nullptr,
        2048, 2048, 2048, 2048, 0, 0, 0, 1.f);
}

// round 15
// speedup vs baseline: 1.0302x; 1.0018x over previous
#include <cuda_runtime.h>
#include <cuda_fp16.h>
#include <cstdint>

// ---------------------------------------------------------------------------
// MultiHeadAttention on GB300 (sm_103a) — legacy mma.sync fp16, 1-term GEMMs.
// R15: GEMMs fixed at the measured legacy-HMMA cap (~540 MAC/cyc/SM); this
// round cuts aux time: warp-per-row softmax (no block barriers), one merged
// fp32->fp16 rounding launch, V-transpose folded into the scores GEMM launch.
// ---------------------------------------------------------------------------

using f16 = __half;

static constexpr long long QKV_ELEMS = 8LL * 1024 * 2048;    // 16,777,216
static constexpr long long W_ELEMS   = 128LL * 1024 * 1024;  // 134,217,728
static constexpr long long WW_ELEMS  = 2048LL * 2048;        // 4,194,304

__device__ f16 g_xq[QKV_ELEMS], g_xk[QKV_ELEMS], g_xv[QKV_ELEMS];
__device__ f16 g_wq[WW_ELEMS], g_wk[WW_ELEMS], g_wv[WW_ELEMS], g_wo[WW_ELEMS];
__device__ f16 g_Qh[QKV_ELEMS], g_Kh[QKV_ELEMS], g_Vh[QKV_ELEMS];
__device__ f16 g_Vth[QKV_ELEMS];
__device__ f16 g_P[W_ELEMS];          // fp16 scores, then probabilities
__device__ f16 g_Ah[QKV_ELEMS];
__device__ float g_WS[W_ELEMS];       // fallback weights if d_out lacks tail

// ------------------------- asm helpers --------------------------------------

__device__ __forceinline__ uint32_t smem_u32(const void* p) {
    uint32_t a;
    asm("{ .reg .u64 t; cvta.to.shared.u64 t, %1; cvt.u32.u64 %0, t; }"
        : "=r"(a) : "l"(p));
    return a;
}

__device__ __forceinline__ void cp16(uint32_t dst, const void* src) {
    asm volatile("cp.async.cg.shared.global [%0], [%1], 16;"
                 :: "r"(dst), "l"(src));
}

__device__ __forceinline__ void ldm_x4(uint32_t* r, uint32_t addr) {
    asm volatile("ldmatrix.sync.aligned.m8n8.x4.shared.b16 {%0,%1,%2,%3}, [%4];"
                 : "=r"(r[0]), "=r"(r[1]), "=r"(r[2]), "=r"(r[3]) : "r"(addr));
}

__device__ __forceinline__ void mma16816(float* c, const uint32_t* a,
                                         uint32_t b0, uint32_t b1) {
    asm volatile(
        "mma.sync.aligned.m16n8k16.row.col.f32.f16.f16.f32 "
        "{%0,%1,%2,%3}, {%4,%5,%6,%7}, {%8,%9}, {%0,%1,%2,%3};"
        : "+f"(c[0]), "+f"(c[1]), "+f"(c[2]), "+f"(c[3])
        : "r"(a[0]), "r"(a[1]), "r"(a[2]), "r"(a[3]), "r"(b0), "r"(b1));
}

__device__ __forceinline__ uint32_t round2h(float v0, float v1) {
    return (uint32_t)__half_as_ushort(__float2half_rn(v0)) |
           ((uint32_t)__half_as_ushort(__float2half_rn(v1)) << 16);
}

// ------------------------- GEMM ---------------------------------------------
// NT: C[m,n] = sum_k A[m,k] * B[n,k], K-major fp16, 1 MMA term.
// CTA tile 128x128, 8 warps of 32x64, occupancy 2, 5-buffer cp.async ring,
// register double-buffered ldmatrix fragments.
// EPI: 0 = fused QKV (3-way select, f16+bias) | 1 = f16*scale (+transpose
//      blocks at blockIdx.y==8) | 2 = f16 | 3 = f32+bias

#define TILE8K 8192
#define STAGE  16384
#define NBUF   5
#define SMEM_TOTAL 81920   // 5 stages x 16KB; epilogue (67.6KB) reuses it

__device__ __forceinline__ uint32_t swz(int row, int cq) {
    return (uint32_t)(row * 64 + ((cq ^ ((row >> 1) & 3)) << 4));
}

template <int EPI>
__global__ __launch_bounds__(256, 2)
void gemm_mma(const f16* __restrict__ A0, const f16* __restrict__ A1,
              const f16* __restrict__ A2,
              const f16* __restrict__ B0, const f16* __restrict__ B1,
              const f16* __restrict__ B2,
              const float* __restrict__ bias0, const float* __restrict__ bias1,
              const float* __restrict__ bias2,
              float* __restrict__ Cf,
              f16* __restrict__ C0, f16* __restrict__ C1, f16* __restrict__ C2,
              int K, int lda, int ldb, int ldc,
              long long sA, long long sB, long long sC, float scale)
{
    extern __shared__ char smem[];
    const uint32_t sb = smem_u32(smem);
    const int tid = threadIdx.x;
    const int wid = tid >> 5;
    const int lane = tid & 31;

    // ---- folded V transpose (scores launch only, grid.y == 8) ----
    if (EPI == 1 && blockIdx.y == 8) {
        // B1 = Vh, B2 = Vth; block x = k-chunk (128 wide), z = slab
        f16* vth = const_cast<f16*>(B2);
        const f16* vh = B1;
        const size_t ib = (size_t)blockIdx.z * 131072;
        const int k0 = blockIdx.x * 128;
        f16 (*tile)[33] = (f16(*)[33])smem;
        const int ty = tid >> 5;             // 0..7
        const int tx = lane;
        #pragma unroll 1
        for (int i = 0; i < 4; i++)          // k sub-block
            #pragma unroll 1
            for (int j = 0; j < 4; j++) {    // d sub-block
                #pragma unroll
                for (int r = 0; r < 4; r++) {
                    const int k = k0 + i * 32 + ty + r * 8;
                    tile[ty + r * 8][tx] = vh[ib + (size_t)k * 128 + j * 32 + tx];
                }
                __syncthreads();
                #pragma unroll
                for (int r = 0; r < 4; r++) {
                    const int d = j * 32 + ty + r * 8;
                    vth[ib + (size_t)d * 1024 + k0 + i * 32 + tx] =
                        tile[tx][ty + r * 8];
                }
                __syncthreads();
            }
        return;
    }

    const int warpM = wid >> 1;          // 0..3 (m tile 32)
    const int warpN = wid & 1;           // 0..1 (n tile 64)

    const int m0 = blockIdx.y * 128;
    const int n0g = blockIdx.x * 128;

    const f16* A;
    const f16* B;
    const float* bias;
    f16* Ch;
    int n0;
    if (EPI == 0) {
        const int sel = n0g >> 11;       // 0:Q 1:K 2:V
        n0 = n0g & 2047;
        A    = (sel == 0) ? A0 : (sel == 1) ? A1 : A2;
        B    = (sel == 0) ? B0 : (sel == 1) ? B1 : B2;
        bias = (sel == 0) ? bias0 : (sel == 1) ? bias1 : bias2;
        Ch   = (sel == 0) ? C0 : (sel == 1) ? C1 : C2;
    } else {
        const long long z = blockIdx.z;
        n0 = n0g;
        A = A0 + z * sA;
        B = B0 + z * sB;
        bias = bias0;
        Ch = (EPI == 3) ? nullptr : C0 + z * sC;
        if (EPI == 3) Cf += z * sC;
    }

    const int NS = K >> 5;
    const int lrow = tid >> 1;
    const int lcq0 = (tid & 1) * 2;

    auto issue_stage = [&](int s, int buf) {
        const int k0 = s << 5;
        const uint32_t base = sb + buf * STAGE;
        #pragma unroll
        for (int t = 0; t < 2; t++) {
            const int cq = lcq0 + t;
            const uint32_t so = swz(lrow, cq);
            cp16(base + so, A + (size_t)(m0 + lrow) * lda + k0 + cq * 8);
            cp16(base + TILE8K + so, B + (size_t)(n0 + lrow) * ldb + k0 + cq * 8);
        }
        asm volatile("cp.async.commit_group;");
    };

    float acc[2][8][4];
    #pragma unroll
    for (int mt = 0; mt < 2; mt++)
        #pragma unroll
        for (int nt = 0; nt < 8; nt++)
            #pragma unroll
            for (int j = 0; j < 4; j++)
                acc[mt][nt][j] = 0.f;

    const int frow = lane & 15;
    const int fhi  = lane >> 4;
    const int arow0 = warpM * 32 + frow;
    const int brow0 = warpN * 64 + frow;

    #pragma unroll
    for (int i = 0; i < 4; i++) {
        if (i < NS) issue_stage(i, i);
        else asm volatile("cp.async.commit_group;");
    }

    int buf = 0;
    for (int s = 0; s < NS; s++) {
        asm volatile("cp.async.wait_group 3;");
        __syncthreads();
        {
            const int nb = (buf + 4 >= NBUF) ? buf - 1 : buf + 4;
            if (s + 4 < NS) issue_stage(s + 4, nb);
            else asm volatile("cp.async.commit_group;");
        }

        const uint32_t stb = sb + buf * STAGE;

        uint32_t aF[2][2][4];
        uint32_t bF[2][2][4];
        #pragma unroll
        for (int mt = 0; mt < 2; mt++)
            ldm_x4(aF[0][mt], stb + swz(arow0 + mt * 16, fhi));
        #pragma unroll
        for (int g = 0; g < 2; g++)
            ldm_x4(bF[0][g], stb + TILE8K + swz(brow0 + g * 16, fhi));

        #pragma unroll
        for (int step = 0; step < 4; step++) {
            const int kq = step >> 1, half = step & 1;
            const int ap = kq & 1, bp = step & 1;
            if (step < 3) {
                const int ns = step + 1;
                const int nkq = ns >> 1, nhalf = ns & 1;
                const int nbp = ns & 1;
                #pragma unroll
                for (int g = 0; g < 2; g++)
                    ldm_x4(bF[nbp][g],
                           stb + TILE8K +
                           swz(brow0 + (nhalf * 2 + g) * 16, nkq * 2 + fhi));
                if (nhalf == 0) {
                    #pragma unroll
                    for (int mt = 0; mt < 2; mt++)
                        ldm_x4(aF[nkq & 1][mt],
                               stb + swz(arow0 + mt * 16, nkq * 2 + fhi));
                }
            }
            #pragma unroll
            for (int mt = 0; mt < 2; mt++)
                #pragma unroll
                for (int t4 = 0; t4 < 4; t4++) {
                    const int g = t4 >> 1, rs = t4 & 1;
                    mma16816(acc[mt][half * 4 + t4], aF[ap][mt],
                             bF[bp][g][rs], bF[bp][g][rs + 2]);
                }
        }
        if (++buf == NBUF) buf = 0;
    }
    __syncthreads();

    // ---- epilogue ----
    {
        const int PITCH = 132;
        float* st = (float*)smem;
        const int tr = lane >> 2;
        const int tc = (lane & 3) * 2;
        #pragma unroll
        for (int mt = 0; mt < 2; mt++)
            #pragma unroll
            for (int nt = 0; nt < 8; nt++) {
                const int r0 = warpM * 32 + mt * 16 + tr;
                const int c0 = warpN * 64 + nt * 8 + tc;
                st[r0 * PITCH + c0]           = acc[mt][nt][0];
                st[r0 * PITCH + c0 + 1]       = acc[mt][nt][1];
                st[(r0 + 8) * PITCH + c0]     = acc[mt][nt][2];
                st[(r0 + 8) * PITCH + c0 + 1] = acc[mt][nt][3];
            }
        __syncthreads();

        const int orow = tid >> 1;
        const int ocb  = (tid & 1) * 64;
        const float* src = st + orow * PITCH + ocb;
        const size_t cbase = (size_t)(m0 + orow) * ldc + n0 + ocb;

        if (EPI == 3) {
            #pragma unroll
            for (int j = 0; j < 64; j += 4) {
                float4 v = *(const float4*)(src + j);
                const float4 b = *(const float4*)(bias + n0 + ocb + j);
                v.x += b.x; v.y += b.y; v.z += b.z; v.w += b.w;
                *(float4*)(Cf + cbase + j) = v;
            }
        } else if (EPI == 0) {
            #pragma unroll
            for (int j = 0; j < 64; j += 2) {
                const float v0 = src[j] + bias[n0 + ocb + j];
                const float v1 = src[j + 1] + bias[n0 + ocb + j + 1];
                *(uint32_t*)(Ch + cbase + j) = round2h(v0, v1);
            }
        } else if (EPI == 1) {
            #pragma unroll
            for (int j = 0; j < 64; j += 2)
                *(uint32_t*)(Ch + cbase + j) =
                    round2h(src[j] * scale, src[j + 1] * scale);
        } else {  // EPI == 2
            #pragma unroll
            for (int j = 0; j < 64; j += 2)
                *(uint32_t*)(Ch + cbase + j) = round2h(src[j], src[j + 1]);
        }
    }
}

// ------------------------- aux kernels --------------------------------------

// merged fp32 -> fp16 rounding: 3 activations (16384 blocks each) then
// 4 weights (4096 blocks each); one flat grid of 65536 blocks.
__global__ __launch_bounds__(256)
void round_all(const float* __restrict__ xq, f16* __restrict__ hq,
               const float* __restrict__ xk, f16* __restrict__ hk,
               const float* __restrict__ xv, f16* __restrict__ hv,
               const float* __restrict__ w0, f16* __restrict__ o0,
               const float* __restrict__ w1, f16* __restrict__ o1,
               const float* __restrict__ w2, f16* __restrict__ o2,
               const float* __restrict__ w3, f16* __restrict__ o3)
{
    const int bid = blockIdx.x;
    const float* x; f16* h; long long base;
    if (bid < 49152) {
        const int seg = bid >> 14;           // 0..2
        x = (seg == 0) ? xq : (seg == 1) ? xk : xv;
        h = (seg == 0) ? hq : (seg == 1) ? hk : hv;
        base = (long long)(bid & 16383) * 256 + threadIdx.x;
    } else {
        const int b = bid - 49152;
        const int seg = b >> 12;             // 0..3
        x = (seg == 0) ? w0 : (seg == 1) ? w1 : (seg == 2) ? w2 : w3;
        h = (seg == 0) ? o0 : (seg == 1) ? o1 : (seg == 2) ? o2 : o3;
        base = (long long)(b & 4095) * 256 + threadIdx.x;
    }
    const float4 v = ((const float4*)x)[base];
    uint2 hu;
    hu.x = round2h(v.x, v.y);
    hu.y = round2h(v.z, v.w);
    ((uint2*)h)[base] = hu;
}

// warp-per-row softmax: 8 rows/block, 32 halves per lane, warp reductions only
__global__ __launch_bounds__(256)
void softmax1024(f16* __restrict__ p, float* __restrict__ wf)
{
    const int tid = threadIdx.x;
    const int wid = tid >> 5;
    const int lane = tid & 31;
    const size_t row = (size_t)blockIdx.x * 8 + wid;
    const size_t rb = row * 1024;

    uint4 u[4];
    const uint4* rp = (const uint4*)(p + rb);
    #pragma unroll
    for (int i = 0; i < 4; i++) u[i] = rp[lane + i * 32];

    float v[32];
    #pragma unroll
    for (int i = 0; i < 4; i++) {
        const __half2* h = (const __half2*)&u[i];
        #pragma unroll
        for (int j = 0; j < 4; j++) {
            v[i * 8 + 2 * j]     = __low2float(h[j]);
            v[i * 8 + 2 * j + 1] = __high2float(h[j]);
        }
    }

    float m = v[0];
    #pragma unroll
    for (int j = 1; j < 32; j++) m = fmaxf(m, v[j]);
    #pragma unroll
    for (int o = 16; o > 0; o >>= 1)
        m = fmaxf(m, __shfl_xor_sync(0xffffffffu, m, o));

    float s = 0.f;
    #pragma unroll
    for (int j = 0; j < 32; j++) { v[j] = __expf(v[j] - m); s += v[j]; }
    #pragma unroll
    for (int o = 16; o > 0; o >>= 1)
        s += __shfl_xor_sync(0xffffffffu, s, o);
    const float inv = 1.0f / s;
    #pragma unroll
    for (int j = 0; j < 32; j++) v[j] *= inv;

    // write fp32 weights: chunk c = lane + 32*i covers float4 ids 2c, 2c+1
    float4* wp = (float4*)(wf + rb);
    #pragma unroll
    for (int i = 0; i < 4; i++) {
        const int c = lane + i * 32;
        wp[2 * c]     = make_float4(v[i * 8 + 0], v[i * 8 + 1],
                                    v[i * 8 + 2], v[i * 8 + 3]);
        wp[2 * c + 1] = make_float4(v[i * 8 + 4], v[i * 8 + 5],
                                    v[i * 8 + 6], v[i * 8 + 7]);
    }
    // write fp16 probabilities in place
    uint4* pp = (uint4*)(p + rb);
    #pragma unroll
    for (int i = 0; i < 4; i++) {
        uint4 o4;
        o4.x = round2h(v[i * 8 + 0], v[i * 8 + 1]);
        o4.y = round2h(v[i * 8 + 2], v[i * 8 + 3]);
        o4.z = round2h(v[i * 8 + 4], v[i * 8 + 5]);
        o4.w = round2h(v[i * 8 + 6], v[i * 8 + 7]);
        pp[lane + i * 32] = o4;
    }
}

// ------------------------- launcher -----------------------------------------

extern "C" void kernel_launch(void* const* d_in, const int* in_sizes, int n_in,
                              void* d_out, int out_size)
{
    (void)in_sizes; (void)n_in;
    const float* query = (const float*)d_in[0];
    const float* key   = (const float*)d_in[1];
    const float* value = (const float*)d_in[2];
    const float* Wq_w  = (const float*)d_in[3];
    const float* Wq_b  = (const float*)d_in[4];
    const float* Wk_w  = (const float*)d_in[5];
    const float* Wk_b  = (const float*)d_in[6];
    const float* Wv_w  = (const float*)d_in[7];
    const float* Wv_b  = (const float*)d_in[8];
    const float* Wo_w  = (const float*)d_in[9];
    const float* Wo_b  = (const float*)d_in[10];

    f16 *xq, *xk, *xv, *wq, *wk, *wv, *wo;
    f16 *Qh, *Kh, *Vh, *Vth, *P, *Ahb;
    float* WS;
    cudaGetSymbolAddress((void**)&xq, g_xq);   cudaGetSymbolAddress((void**)&xk, g_xk);
    cudaGetSymbolAddress((void**)&xv, g_xv);
    cudaGetSymbolAddress((void**)&wq, g_wq);   cudaGetSymbolAddress((void**)&wk, g_wk);
    cudaGetSymbolAddress((void**)&wv, g_wv);   cudaGetSymbolAddress((void**)&wo, g_wo);
    cudaGetSymbolAddress((void**)&Qh, g_Qh);   cudaGetSymbolAddress((void**)&Kh, g_Kh);
    cudaGetSymbolAddress((void**)&Vh, g_Vh);   cudaGetSymbolAddress((void**)&Vth, g_Vth);
    cudaGetSymbolAddress((void**)&P, g_P);     cudaGetSymbolAddress((void**)&Ahb, g_Ah);
    cudaGetSymbolAddress((void**)&WS, g_WS);

    float* out = (float*)d_out;
    float* weights = ((long long)out_size >= QKV_ELEMS + W_ELEMS)
                         ? out + QKV_ELEMS : WS;

    cudaFuncSetAttribute(gemm_mma<0>, cudaFuncAttributeMaxDynamicSharedMemorySize, SMEM_TOTAL);
    cudaFuncSetAttribute(gemm_mma<1>, cudaFuncAttributeMaxDynamicSharedMemorySize, SMEM_TOTAL);
    cudaFuncSetAttribute(gemm_mma<2>, cudaFuncAttributeMaxDynamicSharedMemorySize, SMEM_TOTAL);
    cudaFuncSetAttribute(gemm_mma<3>, cudaFuncAttributeMaxDynamicSharedMemorySize, SMEM_TOTAL);

    const float inv_sqrt_d = 0.022097086912079608f;  // 1/sqrt(2048)
    dim3 blk(256);

    // #0: merged rounds
    round_all<<<65536, blk>>>(query, xq, key, xk, value, xv,
                              Wq_w, wq, Wk_w, wk, Wv_w, wv, Wo_w, wo);

    // #1: fused Q/K/V projections
    gemm_mma<0><<<dim3(48, 64, 1), blk, SMEM_TOTAL>>>(
        xq, xk, xv, wq, wk, wv, Wq_b, Wk_b, Wv_b,
        nullptr, Qh, Kh, Vh,
        2048, 2048, 2048, 2048, 0, 0, 0, 1.f);

    // #2: scores GEMM + folded V transpose (grid.y == 8 blocks)
    gemm_mma<1><<<dim3(8, 9, 128), blk, SMEM_TOTAL>>>(
        Qh, nullptr, nullptr, Kh, Vh, Vth, nullptr, nullptr, nullptr,
        nullptr, P, nullptr, nullptr,
        128, 128, 128, 1024,
        131072LL, 131072LL, 1048576LL, inv_sqrt_d);

    // #3: softmax (profiled slot): fp16 in-place + fp32 weights out
    softmax1024<<<16384, blk>>>(P, weights);

    // #4: attn = P Vt^T -> fp16
    gemm_mma<2><<<dim3(1, 8, 128), blk, SMEM_TOTAL>>>(
        P, nullptr, nullptr, Vth, nullptr, nullptr, nullptr, nullptr, nullptr,
        nullptr, Ahb, nullptr, nullptr,
        1024, 1024, 1024, 128,
        1048576LL, 131072LL, 131072LL, 1.f);

    // #5: out = attn Wo^T + b -> fp32
    gemm_mma<3><<<dim3(16, 64, 1), blk, SMEM_TOTAL>>>(
        Ahb, nullptr, nullptr, wo, nullptr, nullptr, Wo_b, nullptr, nullptr,
        out, nullptr, nullptr, nullptr,
        2048, 2048, 2048, 2048, 0, 0, 0, 1.f);
}